// round 3
// baseline (speedup 1.0000x reference)
#include <cuda_runtime.h>
#include <math.h>
#include <stdint.h>

#define G 4096
#define D 128

#define NEG_BIG (-3.402823466e+38f)
#define LOG2E 1.44269504088896340736f

// ---------- static device scratch ----------
__device__ float g_WcT[256 * 512];   // combined weight, k-major, n' permuted: n' = d*4+gate
__device__ float g_bias[512];        // permuted bias
__device__ float g_h[G * D];
__device__ float g_c[G * D];
__device__ float g_r[G * D];
__device__ float g_h1[D];
__device__ float g_c1[D];
__device__ float g_g1base[512];      // permuted
__device__ int   g_segofs[G + 1];

__device__ __forceinline__ float sigf(float x) { return 1.f / (1.f + __expf(-x)); }

__device__ __forceinline__ float ex2(float x) {
    float r;
    asm("ex2.approx.ftz.f32 %0, %1;" : "=f"(r) : "f"(x));
    return r;
}

__device__ __forceinline__ unsigned long long fma2(unsigned long long a, unsigned long long b,
                                                   unsigned long long c) {
    unsigned long long d;
    asm("fma.rn.f32x2 %0, %1, %2, %3;" : "=l"(d) : "l"(a), "l"(b), "l"(c));
    return d;
}
__device__ __forceinline__ unsigned long long pack2(float v) {
    unsigned long long d;
    asm("mov.b64 %0, {%1, %1};" : "=l"(d) : "f"(v));
    return d;
}

// ---------- setup kernels ----------
// idx: k-major over n so W_ih reads are coalesced.
__global__ void prep_weights(const float* __restrict__ W_ih, const float* __restrict__ W_hh,
                             const float* __restrict__ b_ih, const float* __restrict__ b_hh) {
    int idx = blockIdx.x * blockDim.x + threadIdx.x;
    if (idx < 256 * 512) {
        int n = idx >> 8, k = idx & 255;
        int gate = n >> 7, d = n & 127;
        float w = W_ih[n * 256 + k];
        if (k < 128) w += W_hh[n * 128 + k];
        g_WcT[k * 512 + d * 4 + gate] = w;
    }
    if (idx < 512) {
        int gate = idx >> 7, d = idx & 127;
        g_bias[d * 4 + gate] = b_ih[idx] + b_hh[idx];
    }
}

// Segment boundaries via binary search (index is sorted). Detect int32 vs int64 at runtime.
__global__ void seg_bounds(const int* __restrict__ idx32, int N) {
    int g = blockIdx.x * blockDim.x + threadIdx.x;
    if (g > G) return;
    int j = ((N - 1) & 1) ? (N - 1) : (N - 2);
    bool is64 = (idx32[j] == 0);
    const long long* idx64 = (const long long*)idx32;
    int lo = 0, hi = N;
    while (lo < hi) {
        int mid = (lo + hi) >> 1;
        long long v = is64 ? idx64[mid] : (long long)idx32[mid];
        if (v < (long long)g) lo = mid + 1; else hi = mid;
    }
    g_segofs[g] = lo;
}

// Fused: step-1 closed-form LSTM (state 0) + g1base (rank-1 part of step 2's gates).
__global__ void prep_state() {
    __shared__ float sh1[128];
    int t = threadIdx.x;
    if (t < 128) {
        float i = g_bias[t * 4 + 0], gg = g_bias[t * 4 + 2], o = g_bias[t * 4 + 3];
        float c = sigf(i) * tanhf(gg);
        float h = sigf(o) * tanhf(c);
        g_c1[t] = c;
        g_h1[t] = h;
        sh1[t] = h;
    }
    __syncthreads();
    float acc = g_bias[t];
    #pragma unroll 8
    for (int k = 0; k < 128; k++) acc += sh1[k] * g_WcT[k * 512 + t];
    g_g1base[t] = acc;
}

// ---------- fused GEMM + LSTM cell ----------
// gates[m][n'] = base[n'] + (HAS_A1 ? h@WcT[0:128] : 0) + r@WcT[128:256]; LSTM in epilogue.
// 64x128 tile, grid (64,4) = 256 blocks, 256 threads, 4x8 microtile, BK=8,
// double-buffered smem with register staging, packed f32x2 FFMA.
template <bool HAS_A1, bool CVEC>
__global__ void __launch_bounds__(256) gemm_lstm() {
    __shared__ float As[2][8][64];
    __shared__ float Bs[2][8][128];
    int bm = blockIdx.x;             // 0..63
    int bn = blockIdx.y;             // 0..3
    int t = threadIdx.x;
    int tm = t >> 4, tn = t & 15;
    int arow = t >> 2, ak = (t & 3) * 2;
    int bkk = t >> 5, bnc = (t & 31) * 4;
    unsigned long long acc[4][4] = {};   // 4 rows x 4 col-pairs (8 cols)

    const int kb0 = HAS_A1 ? 0 : 128;
    const int nK = (256 - kb0) >> 3;

    float2 a_st;
    float4 b_st;
    {
        const float* A = (kb0 < 128) ? g_h : g_r;
        a_st = *(const float2*)&A[(size_t)(bm * 64 + arow) * 128 + (kb0 & 127) + ak];
        b_st = *(const float4*)&g_WcT[(kb0 + bkk) * 512 + bn * 128 + bnc];
    }
    As[0][ak][arow] = a_st.x; As[0][ak + 1][arow] = a_st.y;
    *(float4*)&Bs[0][bkk][bnc] = b_st;
    __syncthreads();

    for (int it = 0; it < nK; it++) {
        int buf = it & 1;
        if (it + 1 < nK) {
            int kb = kb0 + ((it + 1) << 3);
            const float* A = (kb < 128) ? g_h : g_r;
            a_st = *(const float2*)&A[(size_t)(bm * 64 + arow) * 128 + (kb & 127) + ak];
            b_st = *(const float4*)&g_WcT[(kb + bkk) * 512 + bn * 128 + bnc];
        }
        #pragma unroll
        for (int kk = 0; kk < 8; kk++) {
            float4 a4 = *(const float4*)&As[buf][kk][tm * 4];
            unsigned long long b0 = *(const unsigned long long*)&Bs[buf][kk][tn * 8 + 0];
            unsigned long long b1 = *(const unsigned long long*)&Bs[buf][kk][tn * 8 + 2];
            unsigned long long b2 = *(const unsigned long long*)&Bs[buf][kk][tn * 8 + 4];
            unsigned long long b3 = *(const unsigned long long*)&Bs[buf][kk][tn * 8 + 6];
            float am[4] = {a4.x, a4.y, a4.z, a4.w};
            #pragma unroll
            for (int mi = 0; mi < 4; mi++) {
                unsigned long long pa = pack2(am[mi]);
                acc[mi][0] = fma2(pa, b0, acc[mi][0]);
                acc[mi][1] = fma2(pa, b1, acc[mi][1]);
                acc[mi][2] = fma2(pa, b2, acc[mi][2]);
                acc[mi][3] = fma2(pa, b3, acc[mi][3]);
            }
        }
        if (it + 1 < nK) {
            int nb = buf ^ 1;
            As[nb][ak][arow] = a_st.x; As[nb][ak + 1][arow] = a_st.y;
            *(float4*)&Bs[nb][bkk][bnc] = b_st;
        }
        __syncthreads();
    }

    // epilogue: thread covers n' = bn*128 + tn*8 .. +7  -> d0 = bn*32 + tn*2, d0+1 (all 4 gates).
    const float* base = HAS_A1 ? g_bias : g_g1base;
    int nbase = bn * 128 + tn * 8;
    float4 bz0 = *(const float4*)&base[nbase];
    float4 bz1 = *(const float4*)&base[nbase + 4];
    int d0 = nbase >> 2;                 // even
    float c01 = 0.f, c02 = 0.f;
    if (CVEC) { c01 = g_c1[d0]; c02 = g_c1[d0 + 1]; }
    #pragma unroll
    for (int mi = 0; mi < 4; mi++) {
        int m = bm * 64 + tm * 4 + mi;
        float2 q0 = *reinterpret_cast<float2*>(&acc[mi][0]);
        float2 q1 = *reinterpret_cast<float2*>(&acc[mi][1]);
        float2 q2 = *reinterpret_cast<float2*>(&acc[mi][2]);
        float2 q3 = *reinterpret_cast<float2*>(&acc[mi][3]);
        float2 coldv;
        if (CVEC) { coldv.x = c01; coldv.y = c02; }
        else      { coldv = *(const float2*)&g_c[(size_t)m * 128 + d0]; }
        float gi0 = q0.x + bz0.x, gf0 = q0.y + bz0.y, gg0 = q1.x + bz0.z, go0 = q1.y + bz0.w;
        float gi1 = q2.x + bz1.x, gf1 = q2.y + bz1.y, gg1 = q3.x + bz1.z, go1 = q3.y + bz1.w;
        float c0 = sigf(gf0) * coldv.x + sigf(gi0) * tanhf(gg0);
        float c1 = sigf(gf1) * coldv.y + sigf(gi1) * tanhf(gg1);
        float h0 = sigf(go0) * tanhf(c0);
        float h1 = sigf(go1) * tanhf(c1);
        float2 cv; cv.x = c0; cv.y = c1;
        float2 hv; hv.x = h0; hv.y = h1;
        *(float2*)&g_c[(size_t)m * 128 + d0] = cv;
        *(float2*)&g_h[(size_t)m * 128 + d0] = hv;
    }
}

// ---------- attention: per-segment online softmax, single pass over x ----------
// One block (128 threads = 4 warps) per segment. Each warp handles 8 rows per iteration
// (2 sets of 4): lane l -> row group (l>>3), columns (l&7)*4 + 32j. State per lane.
template <bool QBCAST, bool FINAL>
__global__ void __launch_bounds__(128) attn_kernel(const float* __restrict__ x,
                                                   float* __restrict__ out) {
    int g = blockIdx.x;
    int start = g_segofs[g], end = g_segofs[g + 1];
    int t = threadIdx.x, w = t >> 5, l = t & 31;
    int i8 = l & 7, grp = l >> 3;
    const float* qrow = QBCAST ? g_h1 : (g_h + (size_t)g * D);

    float4 qv[4];
    #pragma unroll
    for (int j = 0; j < 4; j++) {
        float4 q = *(const float4*)&qrow[i8 * 4 + 32 * j];
        qv[j].x = q.x * LOG2E; qv[j].y = q.y * LOG2E;
        qv[j].z = q.z * LOG2E; qv[j].w = q.w * LOG2E;
    }

    float m = NEG_BIG, s = 0.f;
    float4 acc[4] = {};

    for (int r0 = start + w * 8; r0 < end; r0 += 32) {
        int ra = r0 + grp, rb = r0 + 4 + grp;
        bool va = ra < end, vb = rb < end;
        int rac = va ? ra : end - 1;
        int rbc = vb ? rb : end - 1;
        const float* xra = x + (size_t)rac * D + i8 * 4;
        const float* xrb = x + (size_t)rbc * D + i8 * 4;
        float4 xa[4], xb[4];
        #pragma unroll
        for (int j = 0; j < 4; j++) xa[j] = *(const float4*)&xra[32 * j];
        #pragma unroll
        for (int j = 0; j < 4; j++) xb[j] = *(const float4*)&xrb[32 * j];

        float ea = xa[0].x * qv[0].x + xa[0].y * qv[0].y + xa[0].z * qv[0].z + xa[0].w * qv[0].w;
        float eb = xb[0].x * qv[0].x + xb[0].y * qv[0].y + xb[0].z * qv[0].z + xb[0].w * qv[0].w;
        #pragma unroll
        for (int j = 1; j < 4; j++) {
            ea += xa[j].x * qv[j].x + xa[j].y * qv[j].y + xa[j].z * qv[j].z + xa[j].w * qv[j].w;
            eb += xb[j].x * qv[j].x + xb[j].y * qv[j].y + xb[j].z * qv[j].z + xb[j].w * qv[j].w;
        }
        ea += __shfl_xor_sync(0xffffffffu, ea, 1);
        eb += __shfl_xor_sync(0xffffffffu, eb, 1);
        ea += __shfl_xor_sync(0xffffffffu, ea, 2);
        eb += __shfl_xor_sync(0xffffffffu, eb, 2);
        ea += __shfl_xor_sync(0xffffffffu, ea, 4);
        eb += __shfl_xor_sync(0xffffffffu, eb, 4);

        float eva = va ? ea : NEG_BIG;
        float evb = vb ? eb : NEG_BIG;
        float mn = fmaxf(m, fmaxf(eva, evb));
        float sc = ex2(m - mn);
        float pa = ex2(eva - mn);
        float pb = ex2(evb - mn);
        pa = va ? pa : 0.f;
        pb = vb ? pb : 0.f;
        s = s * sc + pa + pb;
        #pragma unroll
        for (int j = 0; j < 4; j++) {
            acc[j].x = acc[j].x * sc + pa * xa[j].x + pb * xb[j].x;
            acc[j].y = acc[j].y * sc + pa * xa[j].y + pb * xb[j].y;
            acc[j].z = acc[j].z * sc + pa * xa[j].z + pb * xb[j].z;
            acc[j].w = acc[j].w * sc + pa * xa[j].w + pb * xb[j].w;
        }
        m = mn;
    }

    // fold the 4 row-groups within the warp (xor 8, xor 16)
    #pragma unroll
    for (int ofs = 8; ofs <= 16; ofs <<= 1) {
        float m2 = __shfl_xor_sync(0xffffffffu, m, ofs);
        float s2 = __shfl_xor_sync(0xffffffffu, s, ofs);
        float M2 = fmaxf(m, m2);
        float fa = ex2(m - M2), fb = ex2(m2 - M2);
        s = s * fa + s2 * fb;
        #pragma unroll
        for (int j = 0; j < 4; j++) {
            float ox = __shfl_xor_sync(0xffffffffu, acc[j].x, ofs);
            float oy = __shfl_xor_sync(0xffffffffu, acc[j].y, ofs);
            float oz = __shfl_xor_sync(0xffffffffu, acc[j].z, ofs);
            float ow = __shfl_xor_sync(0xffffffffu, acc[j].w, ofs);
            acc[j].x = acc[j].x * fa + ox * fb;
            acc[j].y = acc[j].y * fa + oy * fb;
            acc[j].z = acc[j].z * fa + oz * fb;
            acc[j].w = acc[j].w * fa + ow * fb;
        }
        m = M2;
    }

    __shared__ float sm_m[4], sm_s[4];
    __shared__ float sm_acc[4][128];
    if (l < 8) {
        #pragma unroll
        for (int j = 0; j < 4; j++) *(float4*)&sm_acc[w][i8 * 4 + 32 * j] = acc[j];
        if (l == 0) { sm_m[w] = m; sm_s[w] = s; }
    }
    __syncthreads();

    // t = column 0..127: combine 4 warps
    float M = fmaxf(fmaxf(sm_m[0], sm_m[1]), fmaxf(sm_m[2], sm_m[3]));
    float stot = 0.f, racc = 0.f;
    #pragma unroll
    for (int ww = 0; ww < 4; ww++) {
        float fsc = ex2(sm_m[ww] - M);
        stot += fsc * sm_s[ww];
        racc += fsc * sm_acc[ww][t];
    }
    float r = racc / fmaxf(stot, 1e-16f);
    if (FINAL) {
        out[(size_t)g * 256 + 128 + t] = r;
        out[(size_t)g * 256 + t] = qrow[t];
    } else {
        g_r[(size_t)g * D + t] = r;
    }
}

// ---------- launch ----------
extern "C" void kernel_launch(void* const* d_in, const int* in_sizes, int n_in,
                              void* d_out, int out_size) {
    const float* x    = (const float*)d_in[0];
    const float* W_ih = (const float*)d_in[1];
    const float* W_hh = (const float*)d_in[2];
    const float* b_ih = (const float*)d_in[3];
    const float* b_hh = (const float*)d_in[4];
    const int*   idx  = (const int*)d_in[5];
    float* out = (float*)d_out;
    int N = in_sizes[5];
    (void)n_in; (void)out_size;

    prep_weights<<<(256 * 512 + 255) / 256, 256>>>(W_ih, W_hh, b_ih, b_hh);
    seg_bounds<<<(G + 1 + 255) / 256, 256>>>(idx, N);
    prep_state<<<1, 512>>>();

    // step 1: q = h1 (broadcast) -> r1
    attn_kernel<true, false><<<G, 128>>>(x, out);

    // step 2: gates = g1base + r1 @ WcT[128:256], fused LSTM -> h2, c2
    gemm_lstm<false, true><<<dim3(64, 4), 256>>>();
    attn_kernel<false, false><<<G, 128>>>(x, out);

    // step 3: gates = bias + h2 @ WcT[0:128] + r2 @ WcT[128:256], fused LSTM -> h3, c3
    gemm_lstm<true, false><<<dim3(64, 4), 256>>>();
    attn_kernel<false, true><<<G, 128>>>(x, out);
}

// round 4
// speedup vs baseline: 1.0710x; 1.0710x over previous
#include <cuda_runtime.h>
#include <math.h>
#include <stdint.h>

#define G 4096
#define D 128

#define NEG_BIG (-3.402823466e+38f)
#define LOG2E 1.44269504088896340736f

// ---------- static device scratch ----------
__device__ float g_WcT[256 * 512];   // combined weight, k-major, n' permuted: n' = d*4+gate
__device__ float g_bias[512];        // permuted bias
__device__ float g_h[G * D];
__device__ float g_c[G * D];
__device__ float g_r[G * D];
__device__ float g_gates[G * 512];   // raw GEMM output (no bias), permuted n'
__device__ float g_h1[D];
__device__ float g_c1[D];
__device__ float g_g1base[512];      // permuted
__device__ int   g_segofs[G + 1];

__device__ __forceinline__ float sigf(float x) { return 1.f / (1.f + __expf(-x)); }

__device__ __forceinline__ float ex2(float x) {
    float r;
    asm("ex2.approx.ftz.f32 %0, %1;" : "=f"(r) : "f"(x));
    return r;
}

__device__ __forceinline__ uint32_t f2tf32(float v) {
    uint32_t r;
    asm("cvt.rna.tf32.f32 %0, %1;" : "=r"(r) : "f"(v));
    return r;
}

__device__ __forceinline__ void mma_tf32(float4& d, uint32_t a0, uint32_t a1, uint32_t a2,
                                         uint32_t a3, uint32_t b0, uint32_t b1) {
    asm volatile(
        "mma.sync.aligned.m16n8k8.row.col.f32.tf32.tf32.f32 "
        "{%0,%1,%2,%3}, {%4,%5,%6,%7}, {%8,%9}, {%0,%1,%2,%3};"
        : "+f"(d.x), "+f"(d.y), "+f"(d.z), "+f"(d.w)
        : "r"(a0), "r"(a1), "r"(a2), "r"(a3), "r"(b0), "r"(b1));
}

__device__ __forceinline__ uint2 split_tf32(float v) {
    uint32_t hi = f2tf32(v);
    float lo = v - __uint_as_float(hi);
    uint2 r; r.x = hi; r.y = f2tf32(lo);
    return r;
}

// ---------- setup kernels ----------
__global__ void prep_weights(const float* __restrict__ W_ih, const float* __restrict__ W_hh,
                             const float* __restrict__ b_ih, const float* __restrict__ b_hh) {
    int idx = blockIdx.x * blockDim.x + threadIdx.x;
    if (idx < 256 * 512) {
        int n = idx >> 8, k = idx & 255;
        int gate = n >> 7, d = n & 127;
        float w = W_ih[n * 256 + k];
        if (k < 128) w += W_hh[n * 128 + k];
        g_WcT[k * 512 + d * 4 + gate] = w;
    }
    if (idx < 512) {
        int gate = idx >> 7, d = idx & 127;
        g_bias[d * 4 + gate] = b_ih[idx] + b_hh[idx];
    }
}

// Segment boundaries via binary search (index is sorted). Detect int32 vs int64 at runtime.
__global__ void seg_bounds(const int* __restrict__ idx32, int N) {
    int g = blockIdx.x * blockDim.x + threadIdx.x;
    if (g > G) return;
    int j = ((N - 1) & 1) ? (N - 1) : (N - 2);
    bool is64 = (idx32[j] == 0);
    const long long* idx64 = (const long long*)idx32;
    int lo = 0, hi = N;
    while (lo < hi) {
        int mid = (lo + hi) >> 1;
        long long v = is64 ? idx64[mid] : (long long)idx32[mid];
        if (v < (long long)g) lo = mid + 1; else hi = mid;
    }
    g_segofs[g] = lo;
}

// Fused: step-1 closed-form LSTM (state 0) + g1base (rank-1 part of step 2's gates).
__global__ void prep_state() {
    __shared__ float sh1[128];
    int t = threadIdx.x;
    if (t < 128) {
        float i = g_bias[t * 4 + 0], gg = g_bias[t * 4 + 2], o = g_bias[t * 4 + 3];
        float c = sigf(i) * tanhf(gg);
        float h = sigf(o) * tanhf(c);
        g_c1[t] = c;
        g_h1[t] = h;
        sh1[t] = h;
    }
    __syncthreads();
    float acc = g_bias[t];
    #pragma unroll 8
    for (int k = 0; k < 128; k++) acc += sh1[k] * g_WcT[k * 512 + t];
    g_g1base[t] = acc;
}

// ---------- tensor-core GEMM (tf32 hi/lo split = fp32-accurate) ----------
// gates_raw[m][n'] = (HAS_A1 ? h@WcT[0:128] : 0) + r@WcT[128:256]  (bias added in lstm_elem)
// Block tile 128x128, grid (32,4)=128 blocks (one wave), 8 warps (warp tile 32x64),
// BK=32, single smem buffer + register prefetch. Fragments: m16n8k8 tf32, 3-mma split.
#define AS_STRIDE 36
#define BS_STRIDE 132
#define AS_ELEMS (128 * AS_STRIDE)
#define GEMM_SMEM_BYTES ((AS_ELEMS + 32 * BS_STRIDE) * 8)

template <bool HAS_A1>
__global__ void __launch_bounds__(256) gemm_mma() {
    extern __shared__ uint2 smem_dyn[];
    uint2* As = smem_dyn;                 // [m][k] m<128, k<32, stride 36
    uint2* Bs = smem_dyn + AS_ELEMS;      // [k][n] k<32, n<128, stride 132

    const int bx = blockIdx.x;            // m tile (0..31)
    const int by = blockIdx.y;            // n tile (0..3)
    const int t = threadIdx.x;
    const int wid = t >> 5, l = t & 31;
    const int wm = wid >> 1, wn = wid & 1;          // warp grid 4x2
    const int r = l >> 2, c = l & 3;

    const int m0 = bx * 128;
    const int n0 = by * 128;

    const int NCHUNK = HAS_A1 ? 8 : 4;
    const int KB0 = HAS_A1 ? 0 : 128;

    // staging thread coords
    const int a_row = t >> 3;             // + i*32
    const int a_kq = (t & 7) * 4;
    const int b_k = t >> 5;               // + i*8
    const int b_nq = (t & 31) * 4;

    float4 acc[2][8];
    #pragma unroll
    for (int mi = 0; mi < 2; mi++)
        #pragma unroll
        for (int ni = 0; ni < 8; ni++) acc[mi][ni] = make_float4(0.f, 0.f, 0.f, 0.f);

    float4 a_st[4], b_st[4];

    // load chunk 0
    {
        int kb = KB0;
        const float* A = (kb < 128) ? g_h : g_r;
        int kl = kb & 127;
        #pragma unroll
        for (int i = 0; i < 4; i++)
            a_st[i] = *(const float4*)&A[(size_t)(m0 + a_row + i * 32) * 128 + kl + a_kq];
        #pragma unroll
        for (int i = 0; i < 4; i++)
            b_st[i] = *(const float4*)&g_WcT[(size_t)(kb + b_k + i * 8) * 512 + n0 + b_nq];
    }
    #pragma unroll
    for (int i = 0; i < 4; i++) {
        uint2* d = &As[(a_row + i * 32) * AS_STRIDE + a_kq];
        d[0] = split_tf32(a_st[i].x); d[1] = split_tf32(a_st[i].y);
        d[2] = split_tf32(a_st[i].z); d[3] = split_tf32(a_st[i].w);
        uint2* e = &Bs[(b_k + i * 8) * BS_STRIDE + b_nq];
        e[0] = split_tf32(b_st[i].x); e[1] = split_tf32(b_st[i].y);
        e[2] = split_tf32(b_st[i].z); e[3] = split_tf32(b_st[i].w);
    }
    __syncthreads();

    for (int chunk = 0; chunk < NCHUNK; chunk++) {
        if (chunk + 1 < NCHUNK) {
            int kb = KB0 + (chunk + 1) * 32;
            const float* A = (kb < 128) ? g_h : g_r;
            int kl = kb & 127;
            #pragma unroll
            for (int i = 0; i < 4; i++)
                a_st[i] = *(const float4*)&A[(size_t)(m0 + a_row + i * 32) * 128 + kl + a_kq];
            #pragma unroll
            for (int i = 0; i < 4; i++)
                b_st[i] = *(const float4*)&g_WcT[(size_t)(kb + b_k + i * 8) * 512 + n0 + b_nq];
        }

        #pragma unroll
        for (int ks = 0; ks < 4; ks++) {
            int k0 = ks * 8;
            uint2 af[2][4];
            #pragma unroll
            for (int mi = 0; mi < 2; mi++) {
                int mb = wm * 32 + mi * 16;
                af[mi][0] = As[(mb + r) * AS_STRIDE + k0 + c];
                af[mi][1] = As[(mb + r + 8) * AS_STRIDE + k0 + c];
                af[mi][2] = As[(mb + r) * AS_STRIDE + k0 + c + 4];
                af[mi][3] = As[(mb + r + 8) * AS_STRIDE + k0 + c + 4];
            }
            uint2 bf[8][2];
            #pragma unroll
            for (int ni = 0; ni < 8; ni++) {
                int nb = wn * 64 + ni * 8;
                bf[ni][0] = Bs[(k0 + c) * BS_STRIDE + nb + r];
                bf[ni][1] = Bs[(k0 + c + 4) * BS_STRIDE + nb + r];
            }
            #pragma unroll
            for (int mi = 0; mi < 2; mi++) {
                #pragma unroll
                for (int ni = 0; ni < 8; ni++) {
                    // hi*hi
                    mma_tf32(acc[mi][ni], af[mi][0].x, af[mi][1].x, af[mi][2].x, af[mi][3].x,
                             bf[ni][0].x, bf[ni][1].x);
                    // hi*lo
                    mma_tf32(acc[mi][ni], af[mi][0].x, af[mi][1].x, af[mi][2].x, af[mi][3].x,
                             bf[ni][0].y, bf[ni][1].y);
                    // lo*hi
                    mma_tf32(acc[mi][ni], af[mi][0].y, af[mi][1].y, af[mi][2].y, af[mi][3].y,
                             bf[ni][0].x, bf[ni][1].x);
                }
            }
        }
        __syncthreads();
        if (chunk + 1 < NCHUNK) {
            #pragma unroll
            for (int i = 0; i < 4; i++) {
                uint2* d = &As[(a_row + i * 32) * AS_STRIDE + a_kq];
                d[0] = split_tf32(a_st[i].x); d[1] = split_tf32(a_st[i].y);
                d[2] = split_tf32(a_st[i].z); d[3] = split_tf32(a_st[i].w);
                uint2* e = &Bs[(b_k + i * 8) * BS_STRIDE + b_nq];
                e[0] = split_tf32(b_st[i].x); e[1] = split_tf32(b_st[i].y);
                e[2] = split_tf32(b_st[i].z); e[3] = split_tf32(b_st[i].w);
            }
            __syncthreads();
        }
    }

    // store raw gates
    #pragma unroll
    for (int mi = 0; mi < 2; mi++) {
        int mg = m0 + wm * 32 + mi * 16 + r;
        #pragma unroll
        for (int ni = 0; ni < 8; ni++) {
            int np = n0 + wn * 64 + ni * 8 + 2 * c;
            float2 loa; loa.x = acc[mi][ni].x; loa.y = acc[mi][ni].y;
            float2 hib; hib.x = acc[mi][ni].z; hib.y = acc[mi][ni].w;
            *(float2*)&g_gates[(size_t)mg * 512 + np] = loa;
            *(float2*)&g_gates[(size_t)(mg + 8) * 512 + np] = hib;
        }
    }
}

// ---------- LSTM elementwise: bias add + cell ----------
template <bool CVEC, bool G1BASE>
__global__ void lstm_elem() {
    int idx = blockIdx.x * blockDim.x + threadIdx.x;
    if (idx >= G * D) return;
    int m = idx >> 7, d = idx & 127;
    float4 gv = *(const float4*)&g_gates[(size_t)m * 512 + d * 4];
    const float* base = G1BASE ? g_g1base : g_bias;
    float4 bz = *(const float4*)&base[d * 4];
    float gi = gv.x + bz.x, gf = gv.y + bz.y, gg = gv.z + bz.z, go = gv.w + bz.w;
    float cold = CVEC ? g_c1[d] : g_c[idx];
    float cc = sigf(gf) * cold + sigf(gi) * tanhf(gg);
    g_c[idx] = cc;
    g_h[idx] = sigf(go) * tanhf(cc);
}

// ---------- attention: per-segment online softmax, single pass over x ----------
template <bool QBCAST, bool FINAL>
__global__ void __launch_bounds__(128) attn_kernel(const float* __restrict__ x,
                                                   float* __restrict__ out) {
    int g = blockIdx.x;
    int start = g_segofs[g], end = g_segofs[g + 1];
    int t = threadIdx.x, w = t >> 5, l = t & 31;
    int i8 = l & 7, grp = l >> 3;
    const float* qrow = QBCAST ? g_h1 : (g_h + (size_t)g * D);

    float4 qv[4];
    #pragma unroll
    for (int j = 0; j < 4; j++) {
        float4 q = *(const float4*)&qrow[i8 * 4 + 32 * j];
        qv[j].x = q.x * LOG2E; qv[j].y = q.y * LOG2E;
        qv[j].z = q.z * LOG2E; qv[j].w = q.w * LOG2E;
    }

    float m = NEG_BIG, s = 0.f;
    float4 acc[4] = {};

    for (int r0 = start + w * 8; r0 < end; r0 += 32) {
        int ra = r0 + grp, rb = r0 + 4 + grp;
        bool va = ra < end, vb = rb < end;
        int rac = va ? ra : end - 1;
        int rbc = vb ? rb : end - 1;
        const float* xra = x + (size_t)rac * D + i8 * 4;
        const float* xrb = x + (size_t)rbc * D + i8 * 4;
        float4 xa[4], xb[4];
        #pragma unroll
        for (int j = 0; j < 4; j++) xa[j] = *(const float4*)&xra[32 * j];
        #pragma unroll
        for (int j = 0; j < 4; j++) xb[j] = *(const float4*)&xrb[32 * j];

        float ea = xa[0].x * qv[0].x + xa[0].y * qv[0].y + xa[0].z * qv[0].z + xa[0].w * qv[0].w;
        float eb = xb[0].x * qv[0].x + xb[0].y * qv[0].y + xb[0].z * qv[0].z + xb[0].w * qv[0].w;
        #pragma unroll
        for (int j = 1; j < 4; j++) {
            ea += xa[j].x * qv[j].x + xa[j].y * qv[j].y + xa[j].z * qv[j].z + xa[j].w * qv[j].w;
            eb += xb[j].x * qv[j].x + xb[j].y * qv[j].y + xb[j].z * qv[j].z + xb[j].w * qv[j].w;
        }
        ea += __shfl_xor_sync(0xffffffffu, ea, 1);
        eb += __shfl_xor_sync(0xffffffffu, eb, 1);
        ea += __shfl_xor_sync(0xffffffffu, ea, 2);
        eb += __shfl_xor_sync(0xffffffffu, eb, 2);
        ea += __shfl_xor_sync(0xffffffffu, ea, 4);
        eb += __shfl_xor_sync(0xffffffffu, eb, 4);

        float eva = va ? ea : NEG_BIG;
        float evb = vb ? eb : NEG_BIG;
        float mn = fmaxf(m, fmaxf(eva, evb));
        float sc = ex2(m - mn);
        float pa = ex2(eva - mn);
        float pb = ex2(evb - mn);
        pa = va ? pa : 0.f;
        pb = vb ? pb : 0.f;
        s = s * sc + pa + pb;
        #pragma unroll
        for (int j = 0; j < 4; j++) {
            acc[j].x = acc[j].x * sc + pa * xa[j].x + pb * xb[j].x;
            acc[j].y = acc[j].y * sc + pa * xa[j].y + pb * xb[j].y;
            acc[j].z = acc[j].z * sc + pa * xa[j].z + pb * xb[j].z;
            acc[j].w = acc[j].w * sc + pa * xa[j].w + pb * xb[j].w;
        }
        m = mn;
    }

    #pragma unroll
    for (int ofs = 8; ofs <= 16; ofs <<= 1) {
        float m2 = __shfl_xor_sync(0xffffffffu, m, ofs);
        float s2 = __shfl_xor_sync(0xffffffffu, s, ofs);
        float M2 = fmaxf(m, m2);
        float fa = ex2(m - M2), fb = ex2(m2 - M2);
        s = s * fa + s2 * fb;
        #pragma unroll
        for (int j = 0; j < 4; j++) {
            float ox = __shfl_xor_sync(0xffffffffu, acc[j].x, ofs);
            float oy = __shfl_xor_sync(0xffffffffu, acc[j].y, ofs);
            float oz = __shfl_xor_sync(0xffffffffu, acc[j].z, ofs);
            float ow = __shfl_xor_sync(0xffffffffu, acc[j].w, ofs);
            acc[j].x = acc[j].x * fa + ox * fb;
            acc[j].y = acc[j].y * fa + oy * fb;
            acc[j].z = acc[j].z * fa + oz * fb;
            acc[j].w = acc[j].w * fa + ow * fb;
        }
        m = M2;
    }

    __shared__ float sm_m[4], sm_s[4];
    __shared__ float sm_acc[4][128];
    if (l < 8) {
        #pragma unroll
        for (int j = 0; j < 4; j++) *(float4*)&sm_acc[w][i8 * 4 + 32 * j] = acc[j];
        if (l == 0) { sm_m[w] = m; sm_s[w] = s; }
    }
    __syncthreads();

    float M = fmaxf(fmaxf(sm_m[0], sm_m[1]), fmaxf(sm_m[2], sm_m[3]));
    float stot = 0.f, racc = 0.f;
    #pragma unroll
    for (int ww = 0; ww < 4; ww++) {
        float fsc = ex2(sm_m[ww] - M);
        stot += fsc * sm_s[ww];
        racc += fsc * sm_acc[ww][t];
    }
    float r = racc / fmaxf(stot, 1e-16f);
    if (FINAL) {
        out[(size_t)g * 256 + 128 + t] = r;
        out[(size_t)g * 256 + t] = qrow[t];
    } else {
        g_r[(size_t)g * D + t] = r;
    }
}

// ---------- launch ----------
extern "C" void kernel_launch(void* const* d_in, const int* in_sizes, int n_in,
                              void* d_out, int out_size) {
    const float* x    = (const float*)d_in[0];
    const float* W_ih = (const float*)d_in[1];
    const float* W_hh = (const float*)d_in[2];
    const float* b_ih = (const float*)d_in[3];
    const float* b_hh = (const float*)d_in[4];
    const int*   idx  = (const int*)d_in[5];
    float* out = (float*)d_out;
    int N = in_sizes[5];
    (void)n_in; (void)out_size;

    cudaFuncSetAttribute(gemm_mma<false>, cudaFuncAttributeMaxDynamicSharedMemorySize,
                         GEMM_SMEM_BYTES);
    cudaFuncSetAttribute(gemm_mma<true>, cudaFuncAttributeMaxDynamicSharedMemorySize,
                         GEMM_SMEM_BYTES);

    prep_weights<<<(256 * 512 + 255) / 256, 256>>>(W_ih, W_hh, b_ih, b_hh);
    seg_bounds<<<(G + 1 + 255) / 256, 256>>>(idx, N);
    prep_state<<<1, 512>>>();

    // step 1: q = h1 (broadcast) -> r1
    attn_kernel<true, false><<<G, 128>>>(x, out);

    // step 2: gates = g1base + r1 @ WcT[128:256]
    gemm_mma<false><<<dim3(32, 4), 256, GEMM_SMEM_BYTES>>>();
    lstm_elem<true, true><<<(G * D + 255) / 256, 256>>>();
    attn_kernel<false, false><<<G, 128>>>(x, out);

    // step 3: gates = bias + h2 @ WcT[0:128] + r2 @ WcT[128:256]
    gemm_mma<true><<<dim3(32, 4), 256, GEMM_SMEM_BYTES>>>();
    lstm_elem<false, false><<<(G * D + 255) / 256, 256>>>();
    attn_kernel<false, true><<<G, 128>>>(x, out);
}